// round 1
// baseline (speedup 1.0000x reference)
#include <cuda_runtime.h>
#include <cuda_bf16.h>
#include <math.h>

// ---------------------------------------------------------------------------
// Problem constants
// ---------------------------------------------------------------------------
#define SEQ      4096
#define HIDDEN   2048
#define NHEADS   8
#define NKVHEADS 4
#define HDIM     256
#define CHUNK    2048   // CHUNK_START == 2048, CHUNK_END == 4096
#define QDIM     (NHEADS * HDIM)    // 2048
#define KVDIM    (NKVHEADS * HDIM)  // 1024

// Scratch (device globals — no allocation allowed)
__device__ float g_q [CHUNK * QDIM];     // 16 MB
__device__ float g_k [SEQ * KVDIM];      // 16 MB
__device__ float g_v [SEQ * KVDIM];      // 16 MB
__device__ float g_ao[CHUNK * QDIM];     // 16 MB

// ---------------------------------------------------------------------------
// SGEMM: C[M,N] = A[M,K] @ B[K,N], row-major, all dims multiples of tile sizes
// 128x128 block tile, BK=8, 256 threads, 8x8 micro-tile per thread.
// ---------------------------------------------------------------------------
__global__ __launch_bounds__(256) void sgemm128(
    const float* __restrict__ A, const float* __restrict__ B,
    float* __restrict__ C, int M, int N, int K)
{
    __shared__ float As[8][132];  // transposed A tile: As[k][m]
    __shared__ float Bs[8][132];  // Bs[k][n]

    const int bm = blockIdx.y * 128;
    const int bn = blockIdx.x * 128;
    const int t  = threadIdx.x;
    const int tx = t & 15;   // 0..15  (cols)
    const int ty = t >> 4;   // 0..15  (rows)

    // global load assignments
    const int arow = t >> 1;          // 0..127
    const int acol = (t & 1) * 4;     // 0 or 4
    const int brow = t >> 5;          // 0..7
    const int bcol = (t & 31) * 4;    // 0..124

    float4 acc[2][4][2];              // [rowGrp i][row ii][colGrp j], cols as float4
    #pragma unroll
    for (int i = 0; i < 2; i++)
        #pragma unroll
        for (int ii = 0; ii < 4; ii++)
            #pragma unroll
            for (int j = 0; j < 2; j++)
                acc[i][ii][j] = make_float4(0.f, 0.f, 0.f, 0.f);

    for (int k0 = 0; k0 < K; k0 += 8) {
        float4 av = *(const float4*)&A[(size_t)(bm + arow) * K + k0 + acol];
        float4 bv = *(const float4*)&B[(size_t)(k0 + brow) * N + bn + bcol];
        __syncthreads();
        As[acol + 0][arow] = av.x;
        As[acol + 1][arow] = av.y;
        As[acol + 2][arow] = av.z;
        As[acol + 3][arow] = av.w;
        *(float4*)&Bs[brow][bcol] = bv;
        __syncthreads();

        #pragma unroll
        for (int kk = 0; kk < 8; kk++) {
            float4 a0 = *(float4*)&As[kk][ty * 4];
            float4 a1 = *(float4*)&As[kk][ty * 4 + 64];
            float4 b0 = *(float4*)&Bs[kk][tx * 4];
            float4 b1 = *(float4*)&Bs[kk][tx * 4 + 64];
            float ar[2][4] = {{a0.x, a0.y, a0.z, a0.w}, {a1.x, a1.y, a1.z, a1.w}};
            float4 br[2] = {b0, b1};
            #pragma unroll
            for (int i = 0; i < 2; i++)
                #pragma unroll
                for (int ii = 0; ii < 4; ii++)
                    #pragma unroll
                    for (int j = 0; j < 2; j++) {
                        acc[i][ii][j].x += ar[i][ii] * br[j].x;
                        acc[i][ii][j].y += ar[i][ii] * br[j].y;
                        acc[i][ii][j].z += ar[i][ii] * br[j].z;
                        acc[i][ii][j].w += ar[i][ii] * br[j].w;
                    }
        }
    }

    #pragma unroll
    for (int i = 0; i < 2; i++)
        #pragma unroll
        for (int ii = 0; ii < 4; ii++) {
            int row = bm + ty * 4 + 64 * i + ii;
            #pragma unroll
            for (int j = 0; j < 2; j++)
                *(float4*)&C[(size_t)row * N + bn + tx * 4 + 64 * j] = acc[i][ii][j];
        }
}

// ---------------------------------------------------------------------------
// Fused RMSNorm (+ optional RoPE) over head_dim=256, in place.
// buf layout: (ntokens, nheads*256). block = 128 threads, grid = (ntokens, nheads)
// ---------------------------------------------------------------------------
__global__ __launch_bounds__(128) void norm_rope(
    float* __restrict__ buf, const float* __restrict__ w,
    const float* __restrict__ cosb, const float* __restrict__ sinb,
    int nheads, int pos_off, int use_rope)
{
    const int tok = blockIdx.x;
    const int h   = blockIdx.y;
    float* x = buf + ((size_t)tok * nheads + h) * HDIM;
    const int i = threadIdx.x;           // 0..127

    float x1 = x[i];
    float x2 = x[i + 128];
    float ss = x1 * x1 + x2 * x2;

    // reduce over 128 threads
    #pragma unroll
    for (int off = 16; off > 0; off >>= 1)
        ss += __shfl_xor_sync(0xffffffffu, ss, off);
    __shared__ float wsum[4];
    if ((i & 31) == 0) wsum[i >> 5] = ss;
    __syncthreads();
    float tot = wsum[0] + wsum[1] + wsum[2] + wsum[3];

    float scale = rsqrtf(tot * (1.0f / 256.0f) + 1e-6f);
    float xn1 = x1 * scale * (1.0f + w[i]);
    float xn2 = x2 * scale * (1.0f + w[i + 128]);

    if (use_rope) {
        const size_t p = (size_t)(pos_off + tok) * HDIM;
        float c1 = cosb[p + i],       s1 = sinb[p + i];
        float c2 = cosb[p + i + 128], s2 = sinb[p + i + 128];
        x[i]       = xn1 * c1 - xn2 * s1;   // rotate_half: [:h] gets -x[h:]
        x[i + 128] = xn2 * c2 + xn1 * s2;
    } else {
        x[i]       = xn1;
        x[i + 128] = xn2;
    }
}

// ---------------------------------------------------------------------------
// Flash attention (fp32). BQ=64 q rows, BK=64 k rows, d=256. 256 threads.
// grid = (CHUNK/64, NHEADS). Online softmax, softcap tanh, causal mask.
// K and V share one smem buffer (sequenced by barriers).
// ---------------------------------------------------------------------------
#define FA_KVS 260   // padded row stride for K/V tiles (conflict-free float4 reads)
#define FA_SS  65    // padded row stride for score tile

__global__ __launch_bounds__(256) void flash_attn(
    const float* __restrict__ Qg, const float* __restrict__ Kg,
    const float* __restrict__ Vg, float* __restrict__ Og)
{
    const int qt  = blockIdx.x;
    const int h   = blockIdx.y;
    const int q0  = qt * 64;
    const int kvh = h >> 1;

    extern __shared__ float sm[];
    float* Qs  = sm;                       // 64 * 256
    float* KVs = Qs + 64 * 256;            // 64 * FA_KVS
    float* Ss  = KVs + 64 * FA_KVS;        // 64 * FA_SS
    float* Ms  = Ss + 64 * FA_SS;          // 64
    float* Ls  = Ms + 64;                  // 64
    float* Cs  = Ls + 64;                  // 64

    const int t  = threadIdx.x;
    const int tx = t & 15;
    const int ty = t >> 4;
    const int warp = t >> 5;
    const int lane = t & 31;

    // load Q tile (rows q0..q0+63, head h)
    for (int i = t; i < 64 * 64; i += 256) {
        int r = i >> 6, c4 = i & 63;
        *(float4*)&Qs[r * 256 + c4 * 4] =
            *(const float4*)&Qg[(size_t)(q0 + r) * QDIM + h * HDIM + c4 * 4];
    }
    if (t < 64) { Ms[t] = -1e30f; Ls[t] = 0.f; }

    float4 o[4][4];   // rows ty*4+i, col groups n = 4*(tx+16*j)
    #pragma unroll
    for (int i = 0; i < 4; i++)
        #pragma unroll
        for (int j = 0; j < 4; j++)
            o[i][j] = make_float4(0.f, 0.f, 0.f, 0.f);

    const int qmax = CHUNK + q0 + 63;           // largest global q position in tile
    const int ntiles = (qmax + 1 + 63) >> 6;    // k tiles needed (<= 64)

    for (int kt = 0; kt < ntiles; kt++) {
        const int k0 = kt * 64;
        __syncthreads();   // protect KVs (V reads of prev iter) + Ss (PV reads)

        // load K tile
        for (int i = t; i < 64 * 64; i += 256) {
            int r = i >> 6, c4 = i & 63;
            *(float4*)&KVs[r * FA_KVS + c4 * 4] =
                *(const float4*)&Kg[(size_t)(k0 + r) * KVDIM + kvh * HDIM + c4 * 4];
        }
        __syncthreads();

        // S = Q @ K^T  (raw dot products)
        float s[4][4];
        #pragma unroll
        for (int i = 0; i < 4; i++)
            #pragma unroll
            for (int j = 0; j < 4; j++) s[i][j] = 0.f;

        for (int kd = 0; kd < 256; kd += 4) {
            float4 aq[4], bk[4];
            #pragma unroll
            for (int i = 0; i < 4; i++)
                aq[i] = *(float4*)&Qs[(ty * 4 + i) * 256 + kd];
            #pragma unroll
            for (int j = 0; j < 4; j++)
                bk[j] = *(float4*)&KVs[(tx + 16 * j) * FA_KVS + kd];
            #pragma unroll
            for (int i = 0; i < 4; i++)
                #pragma unroll
                for (int j = 0; j < 4; j++) {
                    s[i][j] += aq[i].x * bk[j].x;
                    s[i][j] += aq[i].y * bk[j].y;
                    s[i][j] += aq[i].z * bk[j].z;
                    s[i][j] += aq[i].w * bk[j].w;
                }
        }
        #pragma unroll
        for (int i = 0; i < 4; i++)
            #pragma unroll
            for (int j = 0; j < 4; j++)
                Ss[(ty * 4 + i) * FA_SS + tx + 16 * j] = s[i][j];
        __syncthreads();

        // load V tile (K no longer needed) — overlaps with softmax below
        for (int i = t; i < 64 * 64; i += 256) {
            int r = i >> 6, c4 = i & 63;
            *(float4*)&KVs[r * FA_KVS + c4 * 4] =
                *(const float4*)&Vg[(size_t)(k0 + r) * KVDIM + kvh * HDIM + c4 * 4];
        }

        // softmax update: warp w owns rows w*8 .. w*8+7
        #pragma unroll
        for (int rr = 0; rr < 8; rr++) {
            const int r = warp * 8 + rr;
            const int qpos = CHUNK + q0 + r;
            float v0 = Ss[r * FA_SS + lane];
            float v1 = Ss[r * FA_SS + lane + 32];
            // logits*scale -> softcap: 50*tanh(l/50); combined: 50*tanh(s*0.0625/50)
            float e0 = 50.f * tanhf(v0 * (0.0625f / 50.f));
            float e1 = 50.f * tanhf(v1 * (0.0625f / 50.f));
            bool m0 = (k0 + lane)      <= qpos;
            bool m1 = (k0 + lane + 32) <= qpos;
            float x0 = m0 ? e0 : -1e30f;
            float x1 = m1 ? e1 : -1e30f;
            float mx = fmaxf(x0, x1);
            #pragma unroll
            for (int off = 16; off > 0; off >>= 1)
                mx = fmaxf(mx, __shfl_xor_sync(0xffffffffu, mx, off));
            float mprev = Ms[r];
            float mnew  = fmaxf(mprev, mx);
            float p0 = m0 ? __expf(x0 - mnew) : 0.f;
            float p1 = m1 ? __expf(x1 - mnew) : 0.f;
            float sum = p0 + p1;
            #pragma unroll
            for (int off = 16; off > 0; off >>= 1)
                sum += __shfl_xor_sync(0xffffffffu, sum, off);
            if (lane == 0) {
                float corr = __expf(mprev - mnew);
                Cs[r] = corr;
                Ls[r] = Ls[r] * corr + sum;
                Ms[r] = mnew;
            }
            Ss[r * FA_SS + lane]      = p0;
            Ss[r * FA_SS + lane + 32] = p1;
        }
        __syncthreads();

        // rescale O accumulators
        float corr[4];
        #pragma unroll
        for (int i = 0; i < 4; i++) corr[i] = Cs[ty * 4 + i];
        #pragma unroll
        for (int i = 0; i < 4; i++)
            #pragma unroll
            for (int j = 0; j < 4; j++) {
                o[i][j].x *= corr[i]; o[i][j].y *= corr[i];
                o[i][j].z *= corr[i]; o[i][j].w *= corr[i];
            }

        // O += P @ V
        for (int k = 0; k < 64; k++) {
            float p[4];
            #pragma unroll
            for (int i = 0; i < 4; i++) p[i] = Ss[(ty * 4 + i) * FA_SS + k];
            float4 v[4];
            #pragma unroll
            for (int j = 0; j < 4; j++)
                v[j] = *(float4*)&KVs[k * FA_KVS + 4 * (tx + 16 * j)];
            #pragma unroll
            for (int i = 0; i < 4; i++)
                #pragma unroll
                for (int j = 0; j < 4; j++) {
                    o[i][j].x += p[i] * v[j].x;
                    o[i][j].y += p[i] * v[j].y;
                    o[i][j].z += p[i] * v[j].z;
                    o[i][j].w += p[i] * v[j].w;
                }
        }
    }

    // epilogue: O / l, write to attn-out buffer (token, head*256+d)
    #pragma unroll
    for (int i = 0; i < 4; i++) {
        float linv = 1.f / Ls[ty * 4 + i];
        int row = q0 + ty * 4 + i;
        #pragma unroll
        for (int j = 0; j < 4; j++) {
            float4 w4 = o[i][j];
            w4.x *= linv; w4.y *= linv; w4.z *= linv; w4.w *= linv;
            *(float4*)&Og[(size_t)row * QDIM + h * HDIM + 4 * (tx + 16 * j)] = w4;
        }
    }
}

// ---------------------------------------------------------------------------
// Launch
// ---------------------------------------------------------------------------
extern "C" void kernel_launch(void* const* d_in, const int* in_sizes, int n_in,
                              void* d_out, int out_size)
{
    const float* X    = (const float*)d_in[0];  // (1, 4096, 2048)
    const float* cosb = (const float*)d_in[1];  // (1, 4096, 256)
    const float* sinb = (const float*)d_in[2];  // (1, 4096, 256)
    // d_in[3] = attention_mask (causal; computed analytically instead)
    const float* wq   = (const float*)d_in[4];  // (2048, 2048)
    const float* wk   = (const float*)d_in[5];  // (2048, 1024)
    const float* wv   = (const float*)d_in[6];  // (2048, 1024)
    const float* wo   = (const float*)d_in[7];  // (2048, 2048)
    const float* qn   = (const float*)d_in[8];
    const float* kn   = (const float*)d_in[9];
    const float* vn   = (const float*)d_in[10];
    float* out = (float*)d_out;

    float *qb, *kb, *vb, *ab;
    cudaGetSymbolAddress((void**)&qb, g_q);
    cudaGetSymbolAddress((void**)&kb, g_k);
    cudaGetSymbolAddress((void**)&vb, g_v);
    cudaGetSymbolAddress((void**)&ab, g_ao);

    // Projections
    sgemm128<<<dim3(QDIM / 128, CHUNK / 128), 256>>>(X + (size_t)CHUNK * HIDDEN, wq, qb,
                                                     CHUNK, QDIM, HIDDEN);
    sgemm128<<<dim3(KVDIM / 128, SEQ / 128), 256>>>(X, wk, kb, SEQ, KVDIM, HIDDEN);
    sgemm128<<<dim3(KVDIM / 128, SEQ / 128), 256>>>(X, wv, vb, SEQ, KVDIM, HIDDEN);

    // RMSNorm (+RoPE for Q/K)
    norm_rope<<<dim3(CHUNK, NHEADS), 128>>>(qb, qn, cosb, sinb, NHEADS, CHUNK, 1);
    norm_rope<<<dim3(SEQ, NKVHEADS), 128>>>(kb, kn, cosb, sinb, NKVHEADS, 0, 1);
    norm_rope<<<dim3(SEQ, NKVHEADS), 128>>>(vb, vn, cosb, sinb, NKVHEADS, 0, 0);

    // Flash attention
    const size_t smem = (64 * 256 + 64 * FA_KVS + 64 * FA_SS + 3 * 64) * sizeof(float);
    cudaFuncSetAttribute(flash_attn, cudaFuncAttributeMaxDynamicSharedMemorySize, (int)smem);
    flash_attn<<<dim3(CHUNK / 64, NHEADS), 256, smem>>>(qb, kb, vb, ab);

    // Output projection
    sgemm128<<<dim3(HIDDEN / 128, CHUNK / 128), 256>>>(ab, wo, out, CHUNK, HIDDEN, QDIM);
}